// round 2
// baseline (speedup 1.0000x reference)
#include <cuda_runtime.h>

#define Bb 4096
#define Nn 256
#define Dd 64
#define Cc 3
#define Mm 32

// Output layout (tuple order, flattened): hi_new[B*D], xi_new[B*C], hj[B*N*D], xj[B*N*C]
#define OUT_XI_OFF   ((size_t)Bb * Dd)
#define OUT_HJ_OFF   (OUT_XI_OFF + (size_t)Bb * Cc)
#define OUT_XJ_OFF   (OUT_HJ_OFF + (size_t)Bb * Nn * Dd)

__device__ __forceinline__ float silu_f(float x) {
    return x / (1.0f + __expf(-x));
}

__global__ __launch_bounds__(256, 2) void e2gn2_kernel(
    const float* __restrict__ hi, const float* __restrict__ xi,
    const float* __restrict__ hj, const float* __restrict__ xj,
    const float* __restrict__ We, const float* __restrict__ be,
    const float* __restrict__ Wx, const float* __restrict__ bx,
    const float* __restrict__ Wx2, const float* __restrict__ bx2,
    const float* __restrict__ Wh, const float* __restrict__ bh,
    float* __restrict__ out)
{
    const int b    = blockIdx.x;
    const int tid  = threadIdx.x;
    const int w    = tid >> 5;     // warp id 0..7
    const int lane = tid & 31;     // lane == m index

    __shared__ __align__(16) float sh_row[8][2][Dd];   // double-buffered hj row per warp
    __shared__ __align__(16) float sh_hi[Dd];
    __shared__ float sh_mi[8][Mm];
    __shared__ float sh_xac[8][4];
    __shared__ float sh_mif[Mm];
    __shared__ float sh_xi[4];

    const float* hi_b = hi + (size_t)b * Dd;
    if (tid < Dd) sh_hi[tid] = hi_b[tid];
    if (tid < Cc) sh_xi[tid] = xi[(size_t)b * Cc + tid];
    __syncthreads();

    const int m = lane;

    // Per-thread resident weights: We_hj[:, m] (rows 64..127 of We)
    float wreg[Dd];
    #pragma unroll
    for (int d = 0; d < Dd; d++) wreg[d] = We[(Dd + d) * Mm + m];
    const float wu0 = We[(2 * Dd + 0) * Mm + m];
    const float wu1 = We[(2 * Dd + 1) * Mm + m];
    const float wu2 = We[(2 * Dd + 2) * Mm + m];
    const float wxr = Wx[m];
    const float bxv = bx[0];

    // base_m = hi . We_hi[:, m] + be[m]
    float base = be[m];
    #pragma unroll
    for (int d = 0; d < Dd; d++) base += sh_hi[d] * We[d * Mm + m];

    const float xi0 = sh_xi[0], xi1 = sh_xi[1], xi2 = sh_xi[2];

    const float2* hj_b   = (const float2*)(hj + (size_t)b * Nn * Dd);
    float2*       out_hj = (float2*)(out + OUT_HJ_OFF + (size_t)b * Nn * Dd);
    const float*  xj_b   = xj + (size_t)b * Nn * Cc;

    float mi_m = 0.0f;
    float xa0 = 0.0f, xa1 = 0.0f, xa2 = 0.0f;

    // warp w handles n = w, w+8, w+16, ...
    float2 pre = hj_b[w * (Dd / 2) + lane];

    for (int k = 0; k < Nn / 8; k++) {
        const int n   = w + 8 * k;
        const int buf = k & 1;

        // stage current row + pass-through write of hj
        *(float2*)&sh_row[w][buf][lane * 2] = pre;
        out_hj[n * (Dd / 2) + lane] = pre;
        // prefetch next row
        if (k < Nn / 8 - 1) pre = hj_b[(n + 8) * (Dd / 2) + lane];
        __syncwarp();

        const float* xjp = xj_b + n * Cc;   // warp-uniform loads
        const float u0 = xi0 - xjp[0];
        const float u1 = xi1 - xjp[1];
        const float u2 = xi2 - xjp[2];

        float acc = base;
        acc += (u0 * u0) * wu0;
        acc += (u1 * u1) * wu1;
        acc += (u2 * u2) * wu2;

        #pragma unroll
        for (int d = 0; d < Dd; d += 4) {
            const float4 h4 = *(const float4*)&sh_row[w][buf][d];
            acc += h4.x * wreg[d + 0];
            acc += h4.y * wreg[d + 1];
            acc += h4.z * wreg[d + 2];
            acc += h4.w * wreg[d + 3];
        }

        const float mv = silu_f(acc);   // mij[b, n, m]
        mi_m += mv;

        // phi_x = silu(sum_m mij*Wx + bx)   (butterfly reduce, all lanes get it)
        float v = mv * wxr;
        #pragma unroll
        for (int off = 16; off; off >>= 1)
            v += __shfl_xor_sync(0xffffffffu, v, off);
        const float px = silu_f(v + bxv);

        xa0 += u0 * px;
        xa1 += u1 * px;
        xa2 += u2 * px;
    }

    sh_mi[w][m] = mi_m;
    if (lane == 0) { sh_xac[w][0] = xa0; sh_xac[w][1] = xa1; sh_xac[w][2] = xa2; }
    __syncthreads();

    if (w == 0) {
        float mt = 0.0f;
        #pragma unroll
        for (int ww = 0; ww < 8; ww++) mt += sh_mi[ww][m];
        sh_mif[m] = mt;

        float v2 = mt * Wx2[m];
        #pragma unroll
        for (int off = 16; off; off >>= 1)
            v2 += __shfl_xor_sync(0xffffffffu, v2, off);
        const float phi2 = silu_f(v2 + bx2[0]);

        if (lane < Cc) {
            float xt = 0.0f;
            #pragma unroll
            for (int ww = 0; ww < 8; ww++) xt += sh_xac[ww][lane];
            out[OUT_XI_OFF + (size_t)b * Cc + lane] =
                sh_xi[lane] * phi2 + xt * (1.0f / (float)Nn);
        }
    }
    __syncthreads();

    // hi_new = silu([hi, mi] @ Wh + bh)
    if (tid < Dd) {
        float acc = bh[tid];
        #pragma unroll 8
        for (int d = 0; d < Dd; d++)  acc += sh_hi[d]  * Wh[d * Dd + tid];
        #pragma unroll 8
        for (int mm = 0; mm < Mm; mm++) acc += sh_mif[mm] * Wh[(Dd + mm) * Dd + tid];
        out[(size_t)b * Dd + tid] = silu_f(acc);
    }
}

extern "C" void kernel_launch(void* const* d_in, const int* in_sizes, int n_in,
                              void* d_out, int out_size) {
    const float* hi  = (const float*)d_in[0];
    const float* xi  = (const float*)d_in[1];
    const float* hj  = (const float*)d_in[2];
    const float* xj  = (const float*)d_in[3];
    const float* We  = (const float*)d_in[4];
    const float* be  = (const float*)d_in[5];
    const float* Wx  = (const float*)d_in[6];
    const float* bx  = (const float*)d_in[7];
    const float* Wx2 = (const float*)d_in[8];
    const float* bx2 = (const float*)d_in[9];
    const float* Wh  = (const float*)d_in[10];
    const float* bh  = (const float*)d_in[11];
    float* out = (float*)d_out;

    // xj pass-through (small: 12.6 MB)
    cudaMemcpyAsync(out + OUT_XJ_OFF, (const void*)xj,
                    (size_t)Bb * Nn * Cc * sizeof(float),
                    cudaMemcpyDeviceToDevice);

    e2gn2_kernel<<<Bb, 256>>>(hi, xi, hj, xj, We, be, Wx, bx, Wx2, bx2, Wh, bh, out);
}

// round 3
// speedup vs baseline: 1.4422x; 1.4422x over previous
#include <cuda_runtime.h>

#define Bb 4096
#define Nn 256
#define Dd 64
#define Cc 3
#define Mm 32

typedef unsigned long long ull;

// Output layout (tuple order, flattened): hi_new[B*D], xi_new[B*C], hj[B*N*D], xj[B*N*C]
#define OUT_XI_OFF   ((size_t)Bb * Dd)
#define OUT_HJ_OFF   (OUT_XI_OFF + (size_t)Bb * Cc)
#define OUT_XJ_OFF   (OUT_HJ_OFF + (size_t)Bb * Nn * Dd)

__device__ __forceinline__ float silu_f(float x) {
    return x / (1.0f + __expf(-x));
}

__device__ __forceinline__ void ffma2(ull& acc, ull a, ull b) {
    asm("fma.rn.f32x2 %0, %1, %2, %0;" : "+l"(acc) : "l"(a), "l"(b));
}
__device__ __forceinline__ ull fadd2(ull a, ull b) {
    ull r; asm("add.rn.f32x2 %0, %1, %2;" : "=l"(r) : "l"(a), "l"(b)); return r;
}
__device__ __forceinline__ float2 unpack2(ull v) {
    float2 r;
    asm("mov.b64 {%0, %1}, %2;" : "=f"(r.x), "=f"(r.y) : "l"(v));
    return r;
}
__device__ __forceinline__ ull pack2(float lo, float hi) {
    ull r; asm("mov.b64 %0, {%1, %2};" : "=l"(r) : "f"(lo), "f"(hi)); return r;
}

__global__ __launch_bounds__(256, 2) void e2gn2_kernel(
    const float* __restrict__ hi, const float* __restrict__ xi,
    const float* __restrict__ hj, const float* __restrict__ xj,
    const float* __restrict__ We, const float* __restrict__ be,
    const float* __restrict__ Wx, const float* __restrict__ bx,
    const float* __restrict__ Wx2, const float* __restrict__ bx2,
    const float* __restrict__ Wh, const float* __restrict__ bh,
    float* __restrict__ out)
{
    const int b    = blockIdx.x;
    const int tid  = threadIdx.x;
    const int w    = tid >> 5;     // warp id 0..7
    const int lane = tid & 31;     // lane == m index

    __shared__ __align__(16) float sh_row[8][2][Dd];   // 2 rows in flight per warp
    __shared__ __align__(16) float sh_hi[Dd];
    __shared__ __align__(16) float sh_xj[Nn * Cc];
    __shared__ float sh_mi[8][Mm];
    __shared__ float sh_xac[8][4];
    __shared__ float sh_mif[Mm];
    __shared__ float sh_xi[4];

    const float* hi_b = hi + (size_t)b * Dd;
    if (tid < Dd) sh_hi[tid] = hi_b[tid];
    if (tid < Cc) sh_xi[tid] = xi[(size_t)b * Cc + tid];
    {   // coalesced xj preload (768 floats)
        const float* xj_b = xj + (size_t)b * Nn * Cc;
        #pragma unroll
        for (int i = 0; i < 3; i++) sh_xj[tid + 256 * i] = xj_b[tid + 256 * i];
    }
    __syncthreads();

    const int m = lane;

    // Per-thread resident weights: We_hj[:, m] packed as f32x2 pairs (d, d+1)
    ull w2[Dd / 2];
    #pragma unroll
    for (int j = 0; j < Dd / 2; j++)
        w2[j] = pack2(We[(Dd + 2 * j) * Mm + m], We[(Dd + 2 * j + 1) * Mm + m]);

    const float wu0 = We[(2 * Dd + 0) * Mm + m];
    const float wu1 = We[(2 * Dd + 1) * Mm + m];
    const float wu2 = We[(2 * Dd + 2) * Mm + m];
    const float wxr = Wx[m];
    const float bxv = bx[0];

    // base_m = hi . We_hi[:, m] + be[m]
    float base = be[m];
    #pragma unroll
    for (int d = 0; d < Dd; d++) base += sh_hi[d] * We[d * Mm + m];

    const float xi0 = sh_xi[0], xi1 = sh_xi[1], xi2 = sh_xi[2];

    const float2* hj_b   = (const float2*)(hj + (size_t)b * Nn * Dd);
    float2*       out_hj = (float2*)(out + OUT_HJ_OFF + (size_t)b * Nn * Dd);

    float mi_m = 0.0f;
    float xa0 = 0.0f, xa1 = 0.0f, xa2 = 0.0f;

    // warp w handles n = w, w+8, w+16, ... ; 2 per iteration
    float2 pre0 = hj_b[(w)     * (Dd / 2) + lane];
    float2 pre1 = hj_b[(w + 8) * (Dd / 2) + lane];

    #pragma unroll 2
    for (int k = 0; k < Nn / 8; k += 2) {
        const int n0 = w + 8 * k;
        const int n1 = n0 + 8;

        // stage rows + pass-through writes
        *(float2*)&sh_row[w][0][lane * 2] = pre0;
        *(float2*)&sh_row[w][1][lane * 2] = pre1;
        out_hj[n0 * (Dd / 2) + lane] = pre0;
        out_hj[n1 * (Dd / 2) + lane] = pre1;
        if (k < Nn / 8 - 2) {
            pre0 = hj_b[(n0 + 16) * (Dd / 2) + lane];
            pre1 = hj_b[(n1 + 16) * (Dd / 2) + lane];
        }
        __syncwarp();

        const float u00 = xi0 - sh_xj[n0 * Cc + 0];
        const float u01 = xi1 - sh_xj[n0 * Cc + 1];
        const float u02 = xi2 - sh_xj[n0 * Cc + 2];
        const float u10 = xi0 - sh_xj[n1 * Cc + 0];
        const float u11 = xi1 - sh_xj[n1 * Cc + 1];
        const float u12 = xi2 - sh_xj[n1 * Cc + 2];

        float base0 = base + (u00 * u00) * wu0 + (u01 * u01) * wu1 + (u02 * u02) * wu2;
        float base1 = base + (u10 * u10) * wu0 + (u11 * u11) * wu1 + (u12 * u12) * wu2;

        // packed dot products: 4 accumulators each, two n interleaved
        ull a0 = 0, a1 = 0, a2 = 0, a3 = 0;   // n0 (0.0f,0.0f packed == 0ull)
        ull c0 = 0, c1 = 0, c2 = 0, c3 = 0;   // n1
        const ulonglong2* r0p = (const ulonglong2*)sh_row[w][0];
        const ulonglong2* r1p = (const ulonglong2*)sh_row[w][1];
        #pragma unroll
        for (int i = 0; i < 16; i += 2) {
            ulonglong2 p = r0p[i],     q = r0p[i + 1];
            ulonglong2 s = r1p[i],     t = r1p[i + 1];
            ffma2(a0, p.x, w2[2 * i + 0]);
            ffma2(a1, p.y, w2[2 * i + 1]);
            ffma2(a2, q.x, w2[2 * i + 2]);
            ffma2(a3, q.y, w2[2 * i + 3]);
            ffma2(c0, s.x, w2[2 * i + 0]);
            ffma2(c1, s.y, w2[2 * i + 1]);
            ffma2(c2, t.x, w2[2 * i + 2]);
            ffma2(c3, t.y, w2[2 * i + 3]);
        }
        a0 = fadd2(fadd2(a0, a1), fadd2(a2, a3));
        c0 = fadd2(fadd2(c0, c1), fadd2(c2, c3));
        const float2 av = unpack2(a0);
        const float2 cv = unpack2(c0);

        const float mv0 = silu_f(base0 + av.x + av.y);   // mij[b, n0, m]
        const float mv1 = silu_f(base1 + cv.x + cv.y);   // mij[b, n1, m]
        mi_m += mv0 + mv1;

        // phi_x = silu(sum_m mij*Wx + bx): two interleaved butterflies
        float v0 = mv0 * wxr;
        float v1 = mv1 * wxr;
        #pragma unroll
        for (int off = 16; off; off >>= 1) {
            v0 += __shfl_xor_sync(0xffffffffu, v0, off);
            v1 += __shfl_xor_sync(0xffffffffu, v1, off);
        }
        const float px0 = silu_f(v0 + bxv);
        const float px1 = silu_f(v1 + bxv);

        xa0 += u00 * px0 + u10 * px1;
        xa1 += u01 * px0 + u11 * px1;
        xa2 += u02 * px0 + u12 * px1;
        __syncwarp();
    }

    sh_mi[w][m] = mi_m;
    if (lane == 0) { sh_xac[w][0] = xa0; sh_xac[w][1] = xa1; sh_xac[w][2] = xa2; }
    __syncthreads();

    if (w == 0) {
        float mt = 0.0f;
        #pragma unroll
        for (int ww = 0; ww < 8; ww++) mt += sh_mi[ww][m];
        sh_mif[m] = mt;

        float v2 = mt * Wx2[m];
        #pragma unroll
        for (int off = 16; off; off >>= 1)
            v2 += __shfl_xor_sync(0xffffffffu, v2, off);
        const float phi2 = silu_f(v2 + bx2[0]);

        if (lane < Cc) {
            float xt = 0.0f;
            #pragma unroll
            for (int ww = 0; ww < 8; ww++) xt += sh_xac[ww][lane];
            out[OUT_XI_OFF + (size_t)b * Cc + lane] =
                sh_xi[lane] * phi2 + xt * (1.0f / (float)Nn);
        }
    }
    __syncthreads();

    // hi_new = silu([hi, mi] @ Wh + bh)
    if (tid < Dd) {
        float acc = bh[tid];
        #pragma unroll 8
        for (int d = 0; d < Dd; d++)  acc += sh_hi[d]  * Wh[d * Dd + tid];
        #pragma unroll 8
        for (int mm = 0; mm < Mm; mm++) acc += sh_mif[mm] * Wh[(Dd + mm) * Dd + tid];
        out[(size_t)b * Dd + tid] = silu_f(acc);
    }
}

extern "C" void kernel_launch(void* const* d_in, const int* in_sizes, int n_in,
                              void* d_out, int out_size) {
    const float* hi  = (const float*)d_in[0];
    const float* xi  = (const float*)d_in[1];
    const float* hj  = (const float*)d_in[2];
    const float* xj  = (const float*)d_in[3];
    const float* We  = (const float*)d_in[4];
    const float* be  = (const float*)d_in[5];
    const float* Wx  = (const float*)d_in[6];
    const float* bx  = (const float*)d_in[7];
    const float* Wx2 = (const float*)d_in[8];
    const float* bx2 = (const float*)d_in[9];
    const float* Wh  = (const float*)d_in[10];
    const float* bh  = (const float*)d_in[11];
    float* out = (float*)d_out;

    // xj pass-through (12.6 MB)
    cudaMemcpyAsync(out + OUT_XJ_OFF, (const void*)xj,
                    (size_t)Bb * Nn * Cc * sizeof(float),
                    cudaMemcpyDeviceToDevice);

    e2gn2_kernel<<<Bb, 256>>>(hi, xi, hj, xj, We, be, Wx, bx, Wx2, bx2, Wh, bh, out);
}

// round 5
// speedup vs baseline: 1.5076x; 1.0454x over previous
#include <cuda_runtime.h>
#include <cuda_bf16.h>
#include <cstdint>

#define Bb 4096
#define Nn 256
#define Dd 64
#define Cc 3
#define Mm 32

typedef unsigned long long ull;

#define OUT_XI_OFF ((size_t)Bb * Dd)
#define OUT_HJ_OFF (OUT_XI_OFF + (size_t)Bb * Cc)
#define OUT_XJ_OFF (OUT_HJ_OFF + (size_t)Bb * Nn * Cc)
// NOTE: hj block is B*N*D; recompute properly below
#undef OUT_XJ_OFF
#define OUT_XJ_OFF (OUT_HJ_OFF + (size_t)Bb * Nn * Dd)

// ---- dynamic smem layout (byte offsets from 1024-aligned base) ----
#define SMO_A_HI  0        // 256 x 64 bf16 = 32768, SW128 swizzled
#define SMO_A_LO  32768    // 32768
#define SMO_BFRAG 65536    // Blo frags: 16 frags x 32 lanes x 8B = 4096
#define SMO_WH    69632    // 96 x 64 fp32 = 24576
#define SMO_WEHI  94208    // 64 x 32 fp32 = 8192
#define SMO_XJ    102400   // 768 fp32 = 3072
#define SMO_HI    105472   // 64 fp32 = 256
#define SMO_BASEC 105728   // 32 x float4 = 512  ({base, wu0, wu1, wu2} per col)
#define SMO_BE    106240   // 32 fp32
#define SMO_WX2   106368   // 32 fp32
#define SMO_MIP   106496   // 8 x 32 fp32 = 1024
#define SMO_XA    107520   // 8 x 4 fp32
#define SMO_MIF   107648   // 32 fp32
#define SMO_XIV   107776   // 4 fp32
#define SMO_SC    107792   // bx, bx2
#define SMEM_TOTAL (107808 + 1024)

__device__ __forceinline__ uint32_t smem_u32(const void* p) {
    uint32_t a;
    asm("{ .reg .u64 t; cvta.to.shared.u64 t, %1; cvt.u32.u64 %0, t; }" : "=r"(a) : "l"(p));
    return a;
}
__device__ __forceinline__ uint32_t swz(uint32_t byte) {  // SW128 swizzle
    return byte ^ ((byte >> 3) & 0x70);
}
__device__ __forceinline__ float silu_f(float x) {
    return x / (1.0f + __expf(-x));
}
__device__ __forceinline__ uint32_t pack_bf16(float lo, float hi) {
    __nv_bfloat162 t = __float22bfloat162_rn(make_float2(lo, hi));
    return *(uint32_t*)&t;
}
__device__ __forceinline__ void ldm_x4(uint32_t& a0, uint32_t& a1,
                                       uint32_t& a2, uint32_t& a3, uint32_t addr) {
    asm volatile("ldmatrix.sync.aligned.m8n8.x4.shared.b16 {%0,%1,%2,%3}, [%4];"
                 : "=r"(a0), "=r"(a1), "=r"(a2), "=r"(a3) : "r"(addr));
}
__device__ __forceinline__ void mma_bf16(float* c, uint32_t a0, uint32_t a1,
                                         uint32_t a2, uint32_t a3,
                                         uint32_t b0, uint32_t b1) {
    asm volatile(
        "mma.sync.aligned.m16n8k16.row.col.f32.bf16.bf16.f32 "
        "{%0,%1,%2,%3}, {%4,%5,%6,%7}, {%8,%9}, {%0,%1,%2,%3};"
        : "+f"(c[0]), "+f"(c[1]), "+f"(c[2]), "+f"(c[3])
        : "r"(a0), "r"(a1), "r"(a2), "r"(a3), "r"(b0), "r"(b1));
}

__global__ __launch_bounds__(256, 2) void e2gn2_kernel(
    const float* __restrict__ hi, const float* __restrict__ xi,
    const float* __restrict__ hj, const float* __restrict__ xj,
    const float* __restrict__ We, const float* __restrict__ be,
    const float* __restrict__ Wx, const float* __restrict__ bx,
    const float* __restrict__ Wx2, const float* __restrict__ bx2,
    const float* __restrict__ Wh, const float* __restrict__ bh,
    float* __restrict__ out)
{
    extern __shared__ char raw_sm[];
    char* sm = (char*)(((uintptr_t)raw_sm + 1023) & ~(uintptr_t)1023);

    const int tid  = threadIdx.x;
    const int w    = tid >> 5;
    const int lane = tid & 31;
    const int q    = lane >> 2;   // row group within warp tiles
    const int s    = lane & 3;    // col-pair group

    float*  smWh   = (float*)(sm + SMO_WH);
    float*  smWeHi = (float*)(sm + SMO_WEHI);
    float*  smXj   = (float*)(sm + SMO_XJ);
    float*  smHi   = (float*)(sm + SMO_HI);
    float4* smBaseC= (float4*)(sm + SMO_BASEC);
    float*  smBe   = (float*)(sm + SMO_BE);
    float*  smWx2  = (float*)(sm + SMO_WX2);
    float*  smMip  = (float*)(sm + SMO_MIP);
    float*  smXa   = (float*)(sm + SMO_XA);
    float*  smMif  = (float*)(sm + SMO_MIF);
    float*  smXiV  = (float*)(sm + SMO_XIV);
    float*  smSc   = (float*)(sm + SMO_SC);
    uint32_t* smBfrag = (uint32_t*)(sm + SMO_BFRAG);

    const uint32_t aHiAddr = smem_u32(sm + SMO_A_HI);
    const uint32_t aLoAddr = smem_u32(sm + SMO_A_LO);

    // ================= one-time init =================
    if (tid == 0) { smSc[0] = bx[0]; smSc[1] = bx2[0]; }
    if (tid < 32) { smBe[tid] = be[tid]; smWx2[tid] = Wx2[tid]; }
    for (int i = tid; i < 2048; i += 256) smWeHi[i] = We[i];
    for (int i = tid; i < 6144; i += 256) smWh[i] = Wh[i];

    // B fragments (We_hj^T, k16n8 col-major frags). Bhi in regs, Blo to smem.
    uint32_t BH0[4][4], BH1[4][4];
    {
        const int nb = (lane >> 2);          // frag col within n8
        const int kb = (lane & 3) * 2;       // frag row pair
        #pragma unroll
        for (int kk = 0; kk < 4; kk++) {
            #pragma unroll
            for (int nt = 0; nt < 4; nt++) {
                const int n  = nt * 8 + nb;
                const int k0 = kk * 16 + kb;
                float v0 = We[(Dd + k0    ) * Mm + n];
                float v1 = We[(Dd + k0 + 1) * Mm + n];
                float v2 = We[(Dd + k0 + 8) * Mm + n];
                float v3 = We[(Dd + k0 + 9) * Mm + n];
                __nv_bfloat16 h0 = __float2bfloat16(v0), h1 = __float2bfloat16(v1);
                __nv_bfloat16 h2 = __float2bfloat16(v2), h3 = __float2bfloat16(v3);
                BH0[kk][nt] = ((uint32_t)*(unsigned short*)&h1 << 16) | *(unsigned short*)&h0;
                BH1[kk][nt] = ((uint32_t)*(unsigned short*)&h3 << 16) | *(unsigned short*)&h2;
                if (w == 0) {
                    float l0 = v0 - __bfloat162float(h0), l1 = v1 - __bfloat162float(h1);
                    float l2 = v2 - __bfloat162float(h2), l3 = v3 - __bfloat162float(h3);
                    smBfrag[((kk * 4 + nt) * 32 + lane) * 2 + 0] = pack_bf16(l0, l1);
                    smBfrag[((kk * 4 + nt) * 32 + lane) * 2 + 1] = pack_bf16(l2, l3);
                }
            }
        }
    }
    // Wx for this thread's 8 columns (col = nt*8 + 2s + j)
    float wxr_[8];
    #pragma unroll
    for (int nt = 0; nt < 4; nt++) {
        wxr_[nt * 2 + 0] = Wx[nt * 8 + 2 * s + 0];
        wxr_[nt * 2 + 1] = Wx[nt * 8 + 2 * s + 1];
    }
    __syncthreads();
    const float bxv  = smSc[0];
    const float bx2v = smSc[1];

    // ================= persistent loop over blocks b =================
    for (int b = blockIdx.x; b < Bb; b += gridDim.x) {

        // ---- stage hj (fp32 -> split bf16, SW128) + hj pass-through ----
        const float4* hj4 = (const float4*)(hj + (size_t)b * Nn * Dd);
        float4*       o4  = (float4*)(out + OUT_HJ_OFF + (size_t)b * Nn * Dd);
        #pragma unroll 4
        for (int g = tid; g < 4096; g += 256) {
            float4 v = hj4[g];
            o4[g] = v;
            int row = g >> 4, grp = g & 15;
            uint32_t off = swz((uint32_t)(row * 128 + grp * 8));
            uint32_t ph0 = pack_bf16(v.x, v.y), ph1 = pack_bf16(v.z, v.w);
            float lx = v.x - __bfloat162float(__float2bfloat16(v.x));
            float ly = v.y - __bfloat162float(__float2bfloat16(v.y));
            float lz = v.z - __bfloat162float(__float2bfloat16(v.z));
            float lw = v.w - __bfloat162float(__float2bfloat16(v.w));
            uint32_t pl0 = pack_bf16(lx, ly), pl1 = pack_bf16(lz, lw);
            *(ull*)(sm + SMO_A_HI + off) = (ull)ph0 | ((ull)ph1 << 32);
            *(ull*)(sm + SMO_A_LO + off) = (ull)pl0 | ((ull)pl1 << 32);
        }
        if (tid < Dd) smHi[tid] = hi[(size_t)b * Dd + tid];
        if (tid < Cc) smXiV[tid] = xi[(size_t)b * Cc + tid];
        for (int i = tid; i < Nn * Cc; i += 256) smXj[i] = xj[(size_t)b * Nn * Cc + i];
        __syncthreads();

        // ---- MMA: warp w owns rows [w*32, w*32+32) ----
        float acc[2][4][4];
        #pragma unroll
        for (int mt = 0; mt < 2; mt++)
            #pragma unroll
            for (int nt = 0; nt < 4; nt++)
                #pragma unroll
                for (int j = 0; j < 4; j++) acc[mt][nt][j] = 0.0f;

        #pragma unroll
        for (int mt = 0; mt < 2; mt++) {
            const int Rm = w * 32 + mt * 16;
            #pragma unroll
            for (int kk = 0; kk < 4; kk++) {
                const uint32_t abyte =
                    swz((uint32_t)((Rm + (lane & 15)) * 128 + kk * 32 + ((lane >> 4) << 4)));
                uint32_t ah0, ah1, ah2, ah3, al0, al1, al2, al3;
                ldm_x4(ah0, ah1, ah2, ah3, aHiAddr + abyte);
                ldm_x4(al0, al1, al2, al3, aLoAddr + abyte);
                #pragma unroll
                for (int nt = 0; nt < 4; nt++) {
                    const uint32_t* blp = smBfrag + ((kk * 4 + nt) * 32 + lane) * 2;
                    uint32_t bl0 = blp[0], bl1 = blp[1];
                    mma_bf16(acc[mt][nt], ah0, ah1, ah2, ah3, BH0[kk][nt], BH1[kk][nt]);
                    mma_bf16(acc[mt][nt], al0, al1, al2, al3, BH0[kk][nt], BH1[kk][nt]);
                    mma_bf16(acc[mt][nt], ah0, ah1, ah2, ah3, bl0, bl1);
                }
            }
        }

        // warp 1: base[m] + per-col constants {base, wu0, wu1, wu2}
        if (w == 1) {
            float sbase = smBe[lane];
            float s0 = 0.f, s1 = 0.f, s2 = 0.f, s3 = 0.f;
            #pragma unroll
            for (int d = 0; d < Dd; d += 4) {
                s0 += smHi[d + 0] * smWeHi[(d + 0) * Mm + lane];
                s1 += smHi[d + 1] * smWeHi[(d + 1) * Mm + lane];
                s2 += smHi[d + 2] * smWeHi[(d + 2) * Mm + lane];
                s3 += smHi[d + 3] * smWeHi[(d + 3) * Mm + lane];
            }
            sbase += (s0 + s1) + (s2 + s3);
            smBaseC[lane] = make_float4(sbase,
                                        __ldg(&We[(2 * Dd + 0) * Mm + lane]),
                                        __ldg(&We[(2 * Dd + 1) * Mm + lane]),
                                        __ldg(&We[(2 * Dd + 2) * Mm + lane]));
        }
        __syncthreads();

        // ---- epilogue ----
        float micol[8];
        #pragma unroll
        for (int j = 0; j < 8; j++) micol[j] = 0.0f;
        float xa0 = 0.f, xa1 = 0.f, xa2 = 0.f;

        #pragma unroll
        for (int mt = 0; mt < 2; mt++) {
            #pragma unroll
            for (int half = 0; half < 2; half++) {
                const int n = w * 32 + mt * 16 + half * 8 + q;
                const float u0 = smXiV[0] - smXj[n * 3 + 0];
                const float u1 = smXiV[1] - smXj[n * 3 + 1];
                const float u2 = smXiV[2] - smXj[n * 3 + 2];
                const float q0 = u0 * u0, q1 = u1 * u1, q2 = u2 * u2;

                float pr = 0.0f;
                #pragma unroll
                for (int nt = 0; nt < 4; nt++) {
                    const int col = nt * 8 + 2 * s;
                    const float4 b0 = smBaseC[col];
                    const float4 b1 = smBaseC[col + 1];
                    float v0 = acc[mt][nt][half * 2 + 0] + b0.x + q0 * b0.y + q1 * b0.z + q2 * b0.w;
                    float v1 = acc[mt][nt][half * 2 + 1] + b1.x + q0 * b1.y + q1 * b1.z + q2 * b1.w;
                    const float mv0 = silu_f(v0);
                    const float mv1 = silu_f(v1);
                    micol[nt * 2 + 0] += mv0;
                    micol[nt * 2 + 1] += mv1;
                    pr += mv0 * wxr_[nt * 2] + mv1 * wxr_[nt * 2 + 1];
                }
                pr += __shfl_xor_sync(0xffffffffu, pr, 1);
                pr += __shfl_xor_sync(0xffffffffu, pr, 2);
                const float px = silu_f(pr + bxv);
                xa0 += u0 * px; xa1 += u1 * px; xa2 += u2 * px;   // 4x redundant per quad
            }
        }

        // mi partial: reduce over q (lanes differing in bits 2..4)
        #pragma unroll
        for (int j = 0; j < 8; j++) {
            micol[j] += __shfl_xor_sync(0xffffffffu, micol[j], 4);
            micol[j] += __shfl_xor_sync(0xffffffffu, micol[j], 8);
            micol[j] += __shfl_xor_sync(0xffffffffu, micol[j], 16);
        }
        if (lane < 4) {
            #pragma unroll
            for (int nt = 0; nt < 4; nt++) {
                smMip[w * 32 + nt * 8 + 2 * lane + 0] = micol[nt * 2 + 0];
                smMip[w * 32 + nt * 8 + 2 * lane + 1] = micol[nt * 2 + 1];
            }
        }
        // xa: butterfly over warp (each row counted 4x -> divide later)
        #pragma unroll
        for (int off = 16; off; off >>= 1) {
            xa0 += __shfl_xor_sync(0xffffffffu, xa0, off);
            xa1 += __shfl_xor_sync(0xffffffffu, xa1, off);
            xa2 += __shfl_xor_sync(0xffffffffu, xa2, off);
        }
        if (lane == 0) { smXa[w*4+0] = xa0; smXa[w*4+1] = xa1; smXa[w*4+2] = xa2; }
        __syncthreads();

        if (w == 0) {
            float mt = 0.0f;
            #pragma unroll
            for (int wi = 0; wi < 8; wi++) mt += smMip[wi * 32 + lane];
            smMif[lane] = mt;
            float v2 = mt * smWx2[lane];
            #pragma unroll
            for (int off = 16; off; off >>= 1)
                v2 += __shfl_xor_sync(0xffffffffu, v2, off);
            const float phi2 = silu_f(v2 + bx2v);
            if (lane < Cc) {
                float xt = 0.0f;
                #pragma unroll
                for (int wi = 0; wi < 8; wi++) xt += smXa[wi * 4 + lane];
                // each row counted 4x in xa -> 1/(4*Nn)
                out[OUT_XI_OFF + (size_t)b * Cc + lane] =
                    smXiV[lane] * phi2 + xt * (1.0f / (4.0f * (float)Nn));
            }
        }
        __syncthreads();

        if (tid < Dd) {
            float a = bh[tid];
            #pragma unroll 8
            for (int d = 0; d < Dd; d++)  a += smHi[d]  * smWh[d * Dd + tid];
            #pragma unroll 8
            for (int m = 0; m < Mm; m++)  a += smMif[m] * smWh[(Dd + m) * Dd + tid];
            out[(size_t)b * Dd + tid] = silu_f(a);
        }
        __syncthreads();   // protect smem before next block's staging
    }
}

extern "C" void kernel_launch(void* const* d_in, const int* in_sizes, int n_in,
                              void* d_out, int out_size) {
    const float* hi  = (const float*)d_in[0];
    const float* xi  = (const float*)d_in[1];
    const float* hj  = (const float*)d_in[2];
    const float* xj  = (const float*)d_in[3];
    const float* We  = (const float*)d_in[4];
    const float* be  = (const float*)d_in[5];
    const float* Wx  = (const float*)d_in[6];
    const float* bx  = (const float*)d_in[7];
    const float* Wx2 = (const float*)d_in[8];
    const float* bx2 = (const float*)d_in[9];
    const float* Wh  = (const float*)d_in[10];
    const float* bh  = (const float*)d_in[11];
    float* out = (float*)d_out;

    cudaMemcpyAsync(out + OUT_XJ_OFF, (const void*)xj,
                    (size_t)Bb * Nn * Cc * sizeof(float),
                    cudaMemcpyDeviceToDevice);

    cudaFuncSetAttribute(e2gn2_kernel,
                         cudaFuncAttributeMaxDynamicSharedMemorySize, SMEM_TOTAL);
    int smCount = 148;
    cudaDeviceGetAttribute(&smCount, cudaDevAttrMultiProcessorCount, 0);
    const int grid = 2 * smCount;

    e2gn2_kernel<<<grid, 256, SMEM_TOTAL>>>(hi, xi, hj, xj, We, be, Wx, bx,
                                            Wx2, bx2, Wh, bh, out);
}

// round 6
// speedup vs baseline: 1.8107x; 1.2010x over previous
#include <cuda_runtime.h>
#include <cuda_bf16.h>
#include <cstdint>

#define Bb 4096
#define Nn 256
#define Dd 64
#define Cc 3
#define Mm 32

typedef unsigned long long ull;

#define OUT_XI_OFF ((size_t)Bb * Dd)
#define OUT_HJ_OFF (OUT_XI_OFF + (size_t)Bb * Cc)
#define OUT_XJ_OFF (OUT_HJ_OFF + (size_t)Bb * Nn * Dd)

// ---- dynamic smem layout (byte offsets from 1024-aligned base) ----
#define SMO_A_HI  0        // 256 x 64 bf16 = 32768, SW128 swizzled
#define SMO_A_LO  32768    // 32768
#define SMO_BFRAG 65536    // Blo frags: 16 frags x 32 lanes x 8B = 4096
#define SMO_WH    69632    // 96 x 64 fp32 = 24576
#define SMO_WEHI  94208    // 64 x 32 fp32 = 8192
#define SMO_XJ    102400   // 768 fp32 = 3072
#define SMO_HI    105472   // 64 fp32 = 256
#define SMO_BASEC 105728   // 32 x float4 = 512  ({base, wu0, wu1, wu2} per col)
#define SMO_BE    106240   // 32 fp32
#define SMO_WX2   106368   // 32 fp32
#define SMO_MIP   106496   // 8 x 32 fp32 = 1024
#define SMO_XA    107520   // 8 x 4 fp32
#define SMO_MIF   107648   // 32 fp32
#define SMO_XIV   107776   // 4 fp32
#define SMO_SC    107792   // bx, bx2
#define SMEM_TOTAL (107808 + 1024)

__device__ __forceinline__ uint32_t smem_u32(const void* p) {
    uint32_t a;
    asm("{ .reg .u64 t; cvta.to.shared.u64 t, %1; cvt.u32.u64 %0, t; }" : "=r"(a) : "l"(p));
    return a;
}
__device__ __forceinline__ uint32_t swz(uint32_t byte) {  // SW128 swizzle
    return byte ^ ((byte >> 3) & 0x70);
}
// fast silu: x * rcp(1 + 2^(-x*log2e)); ex2/rcp approx err ~1e-6 rel
__device__ __forceinline__ float silu_f(float x) {
    float e, r;
    asm("ex2.approx.f32 %0, %1;" : "=f"(e) : "f"(x * -1.442695041f));
    asm("rcp.approx.f32 %0, %1;" : "=f"(r) : "f"(e + 1.0f));
    return x * r;
}
__device__ __forceinline__ uint32_t pack_bf16(float lo, float hi) {
    __nv_bfloat162 t = __float22bfloat162_rn(make_float2(lo, hi));
    return *(uint32_t*)&t;
}
__device__ __forceinline__ void ldm_x4(uint32_t& a0, uint32_t& a1,
                                       uint32_t& a2, uint32_t& a3, uint32_t addr) {
    asm volatile("ldmatrix.sync.aligned.m8n8.x4.shared.b16 {%0,%1,%2,%3}, [%4];"
                 : "=r"(a0), "=r"(a1), "=r"(a2), "=r"(a3) : "r"(addr));
}
__device__ __forceinline__ void mma_bf16(float* c, uint32_t a0, uint32_t a1,
                                         uint32_t a2, uint32_t a3,
                                         uint32_t b0, uint32_t b1) {
    asm volatile(
        "mma.sync.aligned.m16n8k16.row.col.f32.bf16.bf16.f32 "
        "{%0,%1,%2,%3}, {%4,%5,%6,%7}, {%8,%9}, {%0,%1,%2,%3};"
        : "+f"(c[0]), "+f"(c[1]), "+f"(c[2]), "+f"(c[3])
        : "r"(a0), "r"(a1), "r"(a2), "r"(a3), "r"(b0), "r"(b1));
}

__global__ __launch_bounds__(256, 2) void e2gn2_kernel(
    const float* __restrict__ hi, const float* __restrict__ xi,
    const float* __restrict__ hj, const float* __restrict__ xj,
    const float* __restrict__ We, const float* __restrict__ be,
    const float* __restrict__ Wx, const float* __restrict__ bx,
    const float* __restrict__ Wx2, const float* __restrict__ bx2,
    const float* __restrict__ Wh, const float* __restrict__ bh,
    float* __restrict__ out)
{
    extern __shared__ char raw_sm[];
    char* sm = (char*)(((uintptr_t)raw_sm + 1023) & ~(uintptr_t)1023);

    const int tid  = threadIdx.x;
    const int w    = tid >> 5;
    const int lane = tid & 31;
    const int q    = lane >> 2;   // row group within warp tiles
    const int s    = lane & 3;    // col-pair group

    float*  smWh   = (float*)(sm + SMO_WH);
    float*  smWeHi = (float*)(sm + SMO_WEHI);
    float*  smXj   = (float*)(sm + SMO_XJ);
    float*  smHi   = (float*)(sm + SMO_HI);
    float4* smBaseC= (float4*)(sm + SMO_BASEC);
    float*  smBe   = (float*)(sm + SMO_BE);
    float*  smWx2  = (float*)(sm + SMO_WX2);
    float*  smMip  = (float*)(sm + SMO_MIP);
    float*  smXa   = (float*)(sm + SMO_XA);
    float*  smMif  = (float*)(sm + SMO_MIF);
    float*  smXiV  = (float*)(sm + SMO_XIV);
    float*  smSc   = (float*)(sm + SMO_SC);
    uint32_t* smBfrag = (uint32_t*)(sm + SMO_BFRAG);

    const uint32_t aHiAddr = smem_u32(sm + SMO_A_HI);
    const uint32_t aLoAddr = smem_u32(sm + SMO_A_LO);

    // ================= one-time init =================
    if (tid == 0) { smSc[0] = bx[0]; smSc[1] = bx2[0]; }
    if (tid < 32) { smBe[tid] = be[tid]; smWx2[tid] = Wx2[tid]; }
    for (int i = tid; i < 2048; i += 256) smWeHi[i] = We[i];
    for (int i = tid; i < 6144; i += 256) smWh[i] = Wh[i];

    // B fragments (We_hj^T, k16n8 col-major frags). Bhi in regs, Blo to smem.
    uint32_t BH0[4][4], BH1[4][4];
    {
        const int nb = (lane >> 2);
        const int kb = (lane & 3) * 2;
        #pragma unroll
        for (int kk = 0; kk < 4; kk++) {
            #pragma unroll
            for (int nt = 0; nt < 4; nt++) {
                const int n  = nt * 8 + nb;
                const int k0 = kk * 16 + kb;
                float v0 = We[(Dd + k0    ) * Mm + n];
                float v1 = We[(Dd + k0 + 1) * Mm + n];
                float v2 = We[(Dd + k0 + 8) * Mm + n];
                float v3 = We[(Dd + k0 + 9) * Mm + n];
                __nv_bfloat16 h0 = __float2bfloat16(v0), h1 = __float2bfloat16(v1);
                __nv_bfloat16 h2 = __float2bfloat16(v2), h3 = __float2bfloat16(v3);
                BH0[kk][nt] = ((uint32_t)*(unsigned short*)&h1 << 16) | *(unsigned short*)&h0;
                BH1[kk][nt] = ((uint32_t)*(unsigned short*)&h3 << 16) | *(unsigned short*)&h2;
                if (w == 0) {
                    float l0 = v0 - __bfloat162float(h0), l1 = v1 - __bfloat162float(h1);
                    float l2 = v2 - __bfloat162float(h2), l3 = v3 - __bfloat162float(h3);
                    smBfrag[((kk * 4 + nt) * 32 + lane) * 2 + 0] = pack_bf16(l0, l1);
                    smBfrag[((kk * 4 + nt) * 32 + lane) * 2 + 1] = pack_bf16(l2, l3);
                }
            }
        }
    }
    float wxr_[8];
    #pragma unroll
    for (int nt = 0; nt < 4; nt++) {
        wxr_[nt * 2 + 0] = Wx[nt * 8 + 2 * s + 0];
        wxr_[nt * 2 + 1] = Wx[nt * 8 + 2 * s + 1];
    }
    __syncthreads();
    const float bxv  = smSc[0];
    const float bx2v = smSc[1];

    // ================= persistent loop over blocks b =================
    for (int b = blockIdx.x; b < Bb; b += gridDim.x) {

        // ---- stage hj (fp32 -> split bf16, SW128) + pass-through; batched LDG ----
        {
            const float4* hj4 = (const float4*)(hj + (size_t)b * Nn * Dd);
            float4*       o4  = (float4*)(out + OUT_HJ_OFF + (size_t)b * Nn * Dd);
            #pragma unroll
            for (int h = 0; h < 2; h++) {
                float4 v[8];
                #pragma unroll
                for (int i = 0; i < 8; i++) v[i] = hj4[tid + 256 * (h * 8 + i)];
                #pragma unroll
                for (int i = 0; i < 8; i++) {
                    const int g = tid + 256 * (h * 8 + i);
                    o4[g] = v[i];
                    int row = g >> 4, grp = g & 15;
                    uint32_t off = swz((uint32_t)(row * 128 + grp * 8));
                    uint32_t ph0 = pack_bf16(v[i].x, v[i].y), ph1 = pack_bf16(v[i].z, v[i].w);
                    float lx = v[i].x - __bfloat162float(__float2bfloat16(v[i].x));
                    float ly = v[i].y - __bfloat162float(__float2bfloat16(v[i].y));
                    float lz = v[i].z - __bfloat162float(__float2bfloat16(v[i].z));
                    float lw = v[i].w - __bfloat162float(__float2bfloat16(v[i].w));
                    uint32_t pl0 = pack_bf16(lx, ly), pl1 = pack_bf16(lz, lw);
                    *(ull*)(sm + SMO_A_HI + off) = (ull)ph0 | ((ull)ph1 << 32);
                    *(ull*)(sm + SMO_A_LO + off) = (ull)pl0 | ((ull)pl1 << 32);
                }
            }
        }
        if (tid < Dd) smHi[tid] = hi[(size_t)b * Dd + tid];
        if (tid < Cc) smXiV[tid] = xi[(size_t)b * Cc + tid];
        for (int i = tid; i < Nn * Cc; i += 256) smXj[i] = xj[(size_t)b * Nn * Cc + i];
        __syncthreads();

        // ---- MMA: warp w owns rows [w*32, w*32+32) ----
        float acc[2][4][4];
        #pragma unroll
        for (int mt = 0; mt < 2; mt++)
            #pragma unroll
            for (int nt = 0; nt < 4; nt++)
                #pragma unroll
                for (int j = 0; j < 4; j++) acc[mt][nt][j] = 0.0f;

        #pragma unroll
        for (int mt = 0; mt < 2; mt++) {
            const int Rm = w * 32 + mt * 16;
            #pragma unroll
            for (int kk = 0; kk < 4; kk++) {
                const uint32_t abyte =
                    swz((uint32_t)((Rm + (lane & 15)) * 128 + kk * 32 + ((lane >> 4) << 4)));
                uint32_t ah0, ah1, ah2, ah3, al0, al1, al2, al3;
                ldm_x4(ah0, ah1, ah2, ah3, aHiAddr + abyte);
                ldm_x4(al0, al1, al2, al3, aLoAddr + abyte);
                #pragma unroll
                for (int nt = 0; nt < 4; nt++) {
                    const uint32_t* blp = smBfrag + ((kk * 4 + nt) * 32 + lane) * 2;
                    uint32_t bl0 = blp[0], bl1 = blp[1];
                    mma_bf16(acc[mt][nt], ah0, ah1, ah2, ah3, BH0[kk][nt], BH1[kk][nt]);
                    mma_bf16(acc[mt][nt], al0, al1, al2, al3, BH0[kk][nt], BH1[kk][nt]);
                    mma_bf16(acc[mt][nt], ah0, ah1, ah2, ah3, bl0, bl1);
                }
            }
        }

        // warp 1: base[m] + per-col constants {base, wu0, wu1, wu2}
        if (w == 1) {
            float sbase = smBe[lane];
            float s0 = 0.f, s1 = 0.f, s2 = 0.f, s3 = 0.f;
            #pragma unroll
            for (int d = 0; d < Dd; d += 4) {
                s0 += smHi[d + 0] * smWeHi[(d + 0) * Mm + lane];
                s1 += smHi[d + 1] * smWeHi[(d + 1) * Mm + lane];
                s2 += smHi[d + 2] * smWeHi[(d + 2) * Mm + lane];
                s3 += smHi[d + 3] * smWeHi[(d + 3) * Mm + lane];
            }
            sbase += (s0 + s1) + (s2 + s3);
            smBaseC[lane] = make_float4(sbase,
                                        __ldg(&We[(2 * Dd + 0) * Mm + lane]),
                                        __ldg(&We[(2 * Dd + 1) * Mm + lane]),
                                        __ldg(&We[(2 * Dd + 2) * Mm + lane]));
        }
        __syncthreads();

        // ---- epilogue ----
        const float xiv0 = smXiV[0], xiv1 = smXiV[1], xiv2 = smXiV[2];
        float micol[8];
        #pragma unroll
        for (int j = 0; j < 8; j++) micol[j] = 0.0f;
        float xa0 = 0.f, xa1 = 0.f, xa2 = 0.f;

        #pragma unroll
        for (int mt = 0; mt < 2; mt++) {
            #pragma unroll
            for (int half = 0; half < 2; half++) {
                const int n = w * 32 + mt * 16 + half * 8 + q;
                const float u0 = xiv0 - smXj[n * 3 + 0];
                const float u1 = xiv1 - smXj[n * 3 + 1];
                const float u2 = xiv2 - smXj[n * 3 + 2];
                const float q0 = u0 * u0, q1 = u1 * u1, q2 = u2 * u2;

                float pr = 0.0f;
                #pragma unroll
                for (int nt = 0; nt < 4; nt++) {
                    const int col = nt * 8 + 2 * s;
                    const float4 b0 = smBaseC[col];
                    const float4 b1 = smBaseC[col + 1];
                    float v0 = acc[mt][nt][half * 2 + 0] + b0.x + q0 * b0.y + q1 * b0.z + q2 * b0.w;
                    float v1 = acc[mt][nt][half * 2 + 1] + b1.x + q0 * b1.y + q1 * b1.z + q2 * b1.w;
                    const float mv0 = silu_f(v0);
                    const float mv1 = silu_f(v1);
                    micol[nt * 2 + 0] += mv0;
                    micol[nt * 2 + 1] += mv1;
                    pr += mv0 * wxr_[nt * 2] + mv1 * wxr_[nt * 2 + 1];
                }
                pr += __shfl_xor_sync(0xffffffffu, pr, 1);
                pr += __shfl_xor_sync(0xffffffffu, pr, 2);
                const float px = silu_f(pr + bxv);
                xa0 += u0 * px; xa1 += u1 * px; xa2 += u2 * px;   // 4x redundant per quad
            }
        }

        // mi partial: reduce over lanes differing in q bits
        #pragma unroll
        for (int j = 0; j < 8; j++) {
            micol[j] += __shfl_xor_sync(0xffffffffu, micol[j], 4);
            micol[j] += __shfl_xor_sync(0xffffffffu, micol[j], 8);
            micol[j] += __shfl_xor_sync(0xffffffffu, micol[j], 16);
        }
        if (lane < 4) {
            #pragma unroll
            for (int nt = 0; nt < 4; nt++) {
                smMip[w * 32 + nt * 8 + 2 * lane + 0] = micol[nt * 2 + 0];
                smMip[w * 32 + nt * 8 + 2 * lane + 1] = micol[nt * 2 + 1];
            }
        }
        #pragma unroll
        for (int off = 16; off; off >>= 1) {
            xa0 += __shfl_xor_sync(0xffffffffu, xa0, off);
            xa1 += __shfl_xor_sync(0xffffffffu, xa1, off);
            xa2 += __shfl_xor_sync(0xffffffffu, xa2, off);
        }
        if (lane == 0) { smXa[w*4+0] = xa0; smXa[w*4+1] = xa1; smXa[w*4+2] = xa2; }
        __syncthreads();   // smMip/smXa visible; epilogue reads of smXj/BaseC done

        // ---- tail: warp 0 reduce; warps 0-1 final GEMM (named barrier);
        //      warps 2-7 fall through to next block's staging immediately ----
        if (w == 0) {
            float mt = 0.0f;
            #pragma unroll
            for (int wi = 0; wi < 8; wi++) mt += smMip[wi * 32 + lane];
            smMif[lane] = mt;
            float v2 = mt * smWx2[lane];
            #pragma unroll
            for (int off = 16; off; off >>= 1)
                v2 += __shfl_xor_sync(0xffffffffu, v2, off);
            const float phi2 = silu_f(v2 + bx2v);
            if (lane < Cc) {
                float xt = 0.0f;
                #pragma unroll
                for (int wi = 0; wi < 8; wi++) xt += smXa[wi * 4 + lane];
                out[OUT_XI_OFF + (size_t)b * Cc + lane] =
                    smXiV[lane] * phi2 + xt * (1.0f / (4.0f * (float)Nn));
            }
        }
        if (w < 2) {
            asm volatile("bar.sync 1, 64;" ::: "memory");   // smMif ready (warps 0-1 only)
            float a = bh[tid];
            #pragma unroll 8
            for (int d = 0; d < Dd; d++)  a += smHi[d]  * smWh[d * Dd + tid];
            #pragma unroll 8
            for (int m = 0; m < Mm; m++)  a += smMif[m] * smWh[(Dd + m) * Dd + tid];
            out[(size_t)b * Dd + tid] = silu_f(a);
        }
        // next iteration's staging barrier re-syncs all warps
    }
}

extern "C" void kernel_launch(void* const* d_in, const int* in_sizes, int n_in,
                              void* d_out, int out_size) {
    const float* hi  = (const float*)d_in[0];
    const float* xi  = (const float*)d_in[1];
    const float* hj  = (const float*)d_in[2];
    const float* xj  = (const float*)d_in[3];
    const float* We  = (const float*)d_in[4];
    const float* be  = (const float*)d_in[5];
    const float* Wx  = (const float*)d_in[6];
    const float* bx  = (const float*)d_in[7];
    const float* Wx2 = (const float*)d_in[8];
    const float* bx2 = (const float*)d_in[9];
    const float* Wh  = (const float*)d_in[10];
    const float* bh  = (const float*)d_in[11];
    float* out = (float*)d_out;

    cudaMemcpyAsync(out + OUT_XJ_OFF, (const void*)xj,
                    (size_t)Bb * Nn * Cc * sizeof(float),
                    cudaMemcpyDeviceToDevice);

    cudaFuncSetAttribute(e2gn2_kernel,
                         cudaFuncAttributeMaxDynamicSharedMemorySize, SMEM_TOTAL);
    int smCount = 148;
    cudaDeviceGetAttribute(&smCount, cudaDevAttrMultiProcessorCount, 0);
    const int grid = 2 * smCount;

    e2gn2_kernel<<<grid, 256, SMEM_TOTAL>>>(hi, xi, hj, xj, We, be, Wx, bx,
                                            Wx2, bx2, Wh, bh, out);
}